// round 7
// baseline (speedup 1.0000x reference)
#include <cuda_runtime.h>
#include <math.h>

// Problem constants
#define B    32
#define L    2048
#define E    512
#define H    512
#define V    32000
#define D2H  1024          // 2*H
#define SPLITS 32          // L split for k1 reduction

// Output layout (fp32): logp[32000] | h_new[32768] | attn_weights[65536]
#define OUT_LOGP  0
#define OUT_HNEW  32000
#define OUT_ATTN  64768

// GRU GEMM geometry: rows = 2 cells * 3 gates * 512 = 3072, K = 1024(ih) + 512(hh)
#define NROWS 3072
#define ROWT  64            // rows per block tile
#define KSPL  12            // k-splits: 0..7 = ih (128 cols each), 8..11 = hh (128 cols each)
#define KPS   128           // K per split

// -------------------- scratch --------------------
__device__ float4 g_partial[B * SPLITS * (D2H / 4)];   // 4 MB
__device__ float  g_cT[D2H * B];                       // c transposed [k][b]
__device__ float  g_gpart[KSPL][NROWS][B];             // GRU gate partials, 4.7 MB
__device__ float  g_colast[D2H];                       // c_out row 31
__device__ float  g_logits[V];

// -------------------- K1: partial reduce of encoder_out over L --------------------
__global__ void k1_reduce(const float4* __restrict__ enc)
{
    int s = blockIdx.x, b = blockIdx.y, t = threadIdx.x;
    int l0 = s * (L / SPLITS);
    float4 acc = make_float4(0.f, 0.f, 0.f, 0.f);
    const float4* base = enc + (size_t)(b * L + l0) * (D2H / 4) + t;
#pragma unroll 8
    for (int l = 0; l < L / SPLITS; ++l) {
        float4 v = base[(size_t)l * (D2H / 4)];
        acc.x += v.x; acc.y += v.y; acc.z += v.z; acc.w += v.w;
    }
    g_partial[(b * SPLITS + s) * (D2H / 4) + t] = acc;
}

// -------------------- K2: finalize c = relu(mean), store transposed --------------------
__global__ void k2_finalize()
{
    int b = blockIdx.x, t = threadIdx.x;
    float4 acc = make_float4(0.f, 0.f, 0.f, 0.f);
#pragma unroll
    for (int s = 0; s < SPLITS; ++s) {
        float4 v = g_partial[(b * SPLITS + s) * (D2H / 4) + t];
        acc.x += v.x; acc.y += v.y; acc.z += v.z; acc.w += v.w;
    }
    const float inv = 1.0f / (float)L;
    float vals[4] = { acc.x * inv, acc.y * inv, acc.z * inv, acc.w * inv };
#pragma unroll
    for (int i = 0; i < 4; ++i) {
        float c = vals[i] > 0.f ? vals[i] : 0.f;
        g_cT[(4 * t + i) * B + b] = c;
    }
}

// -------------------- K3a: split-K register-tiled GEMM for both GRU cells --------------------
// grid = 48 row-tiles * 12 splits = 576 blocks (~4/SM), 128 threads.
// Thread computes 4 batches x 4 rows. k-tile = 32, K per block = 128.
__global__ void k3a_gemm(const float* __restrict__ h,
                         const float* __restrict__ Wih_f, const float* __restrict__ Whh_f,
                         const float* __restrict__ Wih_b, const float* __restrict__ Whh_b)
{
    int tile  = blockIdx.x / KSPL;
    int split = blockIdx.x % KSPL;
    int R0    = tile * ROWT;           // global row base (0..3071)
    int cell  = (R0 >= 1536) ? 1 : 0;
    int gr0   = R0 - cell * 1536;      // row within this cell's 1536-row W matrix

    const bool   hh   = (split >= 8);
    const float* W    = hh ? (cell ? Whh_b : Whh_f) : (cell ? Wih_b : Wih_f);
    const int    ldw  = hh ? H : D2H;
    const int    koff = hh ? (split - 8) * KPS : split * KPS;

    __shared__ float sW[32][68];       // [k][row], padded
    __shared__ float sX[32][32];       // [k][batch]

    int tid = threadIdx.x;
    int tx  = tid & 7;                 // batch group: batches 4tx..4tx+3
    int ty  = tid >> 3;                // row group:   rows   4ty..4ty+3

    float acc[4][4];
#pragma unroll
    for (int i = 0; i < 4; ++i)
#pragma unroll
        for (int j = 0; j < 4; ++j) acc[i][j] = 0.f;

    const float4* H4  = (const float4*)(h + (size_t)cell * B * H);
    const float4* cT4 = (const float4*)g_cT;

    for (int kt = 0; kt < KPS; kt += 32) {
        // --- load W tile: 64 rows x 32 k, transposed into sW[k][row] ---
#pragma unroll
        for (int i = 0; i < 4; ++i) {
            int idx = tid + i * 128;
            int row = idx >> 3, kg = idx & 7;
            const float4* wr = (const float4*)(W + (size_t)(gr0 + row) * ldw + koff + kt);
            float4 w = wr[kg];
            sW[4 * kg + 0][row] = w.x;
            sW[4 * kg + 1][row] = w.y;
            sW[4 * kg + 2][row] = w.z;
            sW[4 * kg + 3][row] = w.w;
        }
        // --- load X tile into sX[k][b] ---
        if (!hh) {
#pragma unroll
            for (int i = 0; i < 2; ++i) {
                int idx = tid + i * 128;
                int k = idx >> 3, bg = idx & 7;
                ((float4*)&sX[k][0])[bg] = cT4[(size_t)(koff + kt + k) * 8 + bg];
            }
        } else {
#pragma unroll
            for (int i = 0; i < 2; ++i) {
                int idx = tid + i * 128;
                int b = idx >> 3, kg = idx & 7;
                float4 hv = H4[(size_t)b * (H / 4) + ((koff + kt) >> 2) + kg];
                sX[4 * kg + 0][b] = hv.x;
                sX[4 * kg + 1][b] = hv.y;
                sX[4 * kg + 2][b] = hv.z;
                sX[4 * kg + 3][b] = hv.w;
            }
        }
        __syncthreads();

#pragma unroll
        for (int k = 0; k < 32; ++k) {
            float4 a = ((const float4*)&sX[k][0])[tx];
            float4 w = *(const float4*)&sW[k][4 * ty];
            acc[0][0] += a.x * w.x; acc[0][1] += a.x * w.y; acc[0][2] += a.x * w.z; acc[0][3] += a.x * w.w;
            acc[1][0] += a.y * w.x; acc[1][1] += a.y * w.y; acc[1][2] += a.y * w.z; acc[1][3] += a.y * w.w;
            acc[2][0] += a.z * w.x; acc[2][1] += a.z * w.y; acc[2][2] += a.z * w.z; acc[2][3] += a.z * w.w;
            acc[3][0] += a.w * w.x; acc[3][1] += a.w * w.y; acc[3][2] += a.w * w.z; acc[3][3] += a.w * w.w;
        }
        __syncthreads();
    }

#pragma unroll
    for (int j = 0; j < 4; ++j)
#pragma unroll
        for (int i = 0; i < 4; ++i)
            g_gpart[split][R0 + 4 * ty + j][4 * tx + i] = acc[i][j];
}

// -------------------- K3b: combine partials + gates + nonlinearity --------------------
__device__ __forceinline__ float sigmoidf_(float x) { return 1.0f / (1.0f + expf(-x)); }

__global__ void k3b_gate(const float* __restrict__ h,
                         const float* __restrict__ bih_f, const float* __restrict__ bhh_f,
                         const float* __restrict__ bih_b, const float* __restrict__ bhh_b,
                         float* __restrict__ out)
{
    int idx  = blockIdx.x * 256 + threadIdx.x;
    int b    = idx & 31;
    int j    = (idx >> 5) & 511;
    int cell = idx >> 14;

    const float* bih = cell ? bih_b : bih_f;
    const float* bhh = cell ? bhh_b : bhh_f;
    int Rb = cell * 1536;

    float Gi[3], Gh[3];
#pragma unroll
    for (int g = 0; g < 3; ++g) {
        int R = Rb + g * 512 + j;
        float gi = bih[g * 512 + j];
#pragma unroll
        for (int s = 0; s < 8; ++s) gi += g_gpart[s][R][b];
        float gh = bhh[g * 512 + j];
#pragma unroll
        for (int s = 8; s < 12; ++s) gh += g_gpart[s][R][b];
        Gi[g] = gi; Gh[g] = gh;
    }
    float hprev = h[(size_t)cell * B * H + b * H + j];
    float r = sigmoidf_(Gi[0] + Gh[0]);
    float z = sigmoidf_(Gi[1] + Gh[1]);
    float n = tanhf(Gi[2] + r * Gh[2]);
    float hn = (1.0f - z) * n + z * hprev;

    out[OUT_HNEW + cell * B * H + b * H + j] = hn;
    if (b == B - 1) g_colast[cell * H + j] = hn;
}

// -------------------- K4: vocab GEMV --------------------
__global__ void k4_logits(const float4* __restrict__ outW, const float* __restrict__ outb)
{
    __shared__ float4 sc[D2H / 4];
    int tid = threadIdx.x;
    sc[tid] = ((const float4*)g_colast)[tid];
    __syncthreads();

    int warp = tid >> 5, lane = tid & 31;
    int v = blockIdx.x * 8 + warp;
    const float4* wrow = outW + (size_t)v * (D2H / 4);
    float acc = 0.f;
#pragma unroll
    for (int i = 0; i < 8; ++i) {
        float4 w = wrow[lane + 32 * i];
        float4 c = sc[lane + 32 * i];
        acc += w.x * c.x + w.y * c.y + w.z * c.z + w.w * c.w;
    }
#pragma unroll
    for (int o = 16; o; o >>= 1) acc += __shfl_xor_sync(0xFFFFFFFFu, acc, o);
    if (lane == 0) g_logits[v] = acc + outb[v];
}

// -------------------- K5: log_softmax --------------------
__global__ void k5_logp(float* __restrict__ out)
{
    const float4* L4 = (const float4*)g_logits;
    int tid = threadIdx.x;
    __shared__ float red[32];
    __shared__ float bval;

    float m = -1e30f;
    for (int i = tid; i < V / 4; i += 1024) {
        float4 v = L4[i];
        m = fmaxf(m, fmaxf(fmaxf(v.x, v.y), fmaxf(v.z, v.w)));
    }
#pragma unroll
    for (int o = 16; o; o >>= 1) m = fmaxf(m, __shfl_xor_sync(0xFFFFFFFFu, m, o));
    if ((tid & 31) == 0) red[tid >> 5] = m;
    __syncthreads();
    if (tid < 32) {
        float t = red[tid];
#pragma unroll
        for (int o = 16; o; o >>= 1) t = fmaxf(t, __shfl_xor_sync(0xFFFFFFFFu, t, o));
        if (tid == 0) bval = t;
    }
    __syncthreads();
    m = bval;
    __syncthreads();

    float s = 0.f;
    for (int i = tid; i < V / 4; i += 1024) {
        float4 v = L4[i];
        s += expf(v.x - m) + expf(v.y - m) + expf(v.z - m) + expf(v.w - m);
    }
#pragma unroll
    for (int o = 16; o; o >>= 1) s += __shfl_xor_sync(0xFFFFFFFFu, s, o);
    if ((tid & 31) == 0) red[tid >> 5] = s;
    __syncthreads();
    if (tid < 32) {
        float t = red[tid];
#pragma unroll
        for (int o = 16; o; o >>= 1) t += __shfl_xor_sync(0xFFFFFFFFu, t, o);
        if (tid == 0) bval = m + logf(t);
    }
    __syncthreads();
    float lse = bval;

    float4* O4 = (float4*)(out + OUT_LOGP);
    for (int i = tid; i < V / 4; i += 1024) {
        float4 v = L4[i];
        v.x -= lse; v.y -= lse; v.z -= lse; v.w -= lse;
        O4[i] = v;
    }
}

// -------------------- K6: attn_weights = 1/L --------------------
__global__ void k6_attn(float* __restrict__ out)
{
    float4* O4 = (float4*)(out + OUT_ATTN);
    int idx = blockIdx.x * blockDim.x + threadIdx.x;
    const float w = 1.0f / (float)L;
    O4[idx] = make_float4(w, w, w, w);
}

// -------------------- launch --------------------
extern "C" void kernel_launch(void* const* d_in, const int* in_sizes, int n_in,
                              void* d_out, int out_size)
{
    (void)in_sizes; (void)n_in; (void)out_size;
    const float* h_in   = (const float*)d_in[1];
    const float* enc    = (const float*)d_in[2];
    const float* Wih_f  = (const float*)d_in[6];
    const float* Whh_f  = (const float*)d_in[7];
    const float* bih_f  = (const float*)d_in[8];
    const float* bhh_f  = (const float*)d_in[9];
    const float* Wih_b  = (const float*)d_in[10];
    const float* Whh_b  = (const float*)d_in[11];
    const float* bih_b  = (const float*)d_in[12];
    const float* bhh_b  = (const float*)d_in[13];
    const float* outW   = (const float*)d_in[14];
    const float* outb   = (const float*)d_in[15];
    float* out = (float*)d_out;

    k6_attn<<<64, 256>>>(out);

    k1_reduce<<<dim3(SPLITS, B), 256>>>((const float4*)enc);
    k2_finalize<<<B, 256>>>();

    k3a_gemm<<<(NROWS / ROWT) * KSPL, 128>>>(h_in, Wih_f, Whh_f, Wih_b, Whh_b);
    k3b_gate<<<(2 * B * H) / 256, 256>>>(h_in, bih_f, bhh_f, bih_b, bhh_b, out);

    k4_logits<<<V / 8, 256>>>((const float4*)outW, outb);
    k5_logp<<<1, 1024>>>(out);
}

// round 8
// speedup vs baseline: 1.1887x; 1.1887x over previous
#include <cuda_runtime.h>
#include <math.h>

// Problem constants
#define B    32
#define L    2048
#define E    512
#define H    512
#define V    32000
#define D2H  1024          // 2*H
#define SPLITS 32          // L split for k1 reduction

// Output layout (fp32): logp[32000] | h_new[32768] | attn_weights[65536]
#define OUT_LOGP  0
#define OUT_HNEW  32000
#define OUT_ATTN  64768

// GRU GEMM geometry: rows = 2 cells * 3 gates * 512 = 3072, K = 1024(ih) + 512(hh)
#define NROWS 3072
#define ROWT  64            // rows per block tile
#define KSPL  24            // k-splits: 0..15 = ih (64 cols each), 16..23 = hh (64 cols each)
#define KPS   64            // K per split

// -------------------- scratch --------------------
__device__ float4 g_partial[B * SPLITS * (D2H / 4)];   // 4 MB
__device__ float  g_cT[D2H * B];                       // c transposed [k][b]
__device__ float  g_gpart[KSPL][NROWS][B];             // GRU gate partials, 9.4 MB
__device__ float  g_colast[D2H];                       // c_out row 31
__device__ float  g_logits[V];
__device__ float2 g_lse[32];                           // per-block (max, sumexp)

// -------------------- K1: partial reduce of encoder_out over L (+ attn fill) --------------------
__global__ void k1_reduce(const float4* __restrict__ enc, float* __restrict__ out)
{
    int s = blockIdx.x, b = blockIdx.y, t = threadIdx.x;
    int l0 = s * (L / SPLITS);
    float4 acc = make_float4(0.f, 0.f, 0.f, 0.f);
    const float4* base = enc + (size_t)(b * L + l0) * (D2H / 4) + t;
#pragma unroll 8
    for (int l = 0; l < L / SPLITS; ++l) {
        float4 v = base[(size_t)l * (D2H / 4)];
        acc.x += v.x; acc.y += v.y; acc.z += v.z; acc.w += v.w;
    }
    g_partial[(b * SPLITS + s) * (D2H / 4) + t] = acc;

    // fold in constant attn_weights fill: 1024 blocks x 16 float4 = 16384 float4
    if (t < 16) {
        int fid = b * SPLITS + s;
        const float w = 1.0f / (float)L;
        ((float4*)(out + OUT_ATTN))[fid * 16 + t] = make_float4(w, w, w, w);
    }
}

// -------------------- K2: finalize c = relu(mean), store transposed --------------------
__global__ void k2_finalize()
{
    int b = blockIdx.x, t = threadIdx.x;
    float4 acc = make_float4(0.f, 0.f, 0.f, 0.f);
#pragma unroll
    for (int s = 0; s < SPLITS; ++s) {
        float4 v = g_partial[(b * SPLITS + s) * (D2H / 4) + t];
        acc.x += v.x; acc.y += v.y; acc.z += v.z; acc.w += v.w;
    }
    const float inv = 1.0f / (float)L;
    float vals[4] = { acc.x * inv, acc.y * inv, acc.z * inv, acc.w * inv };
#pragma unroll
    for (int i = 0; i < 4; ++i) {
        float c = vals[i] > 0.f ? vals[i] : 0.f;
        g_cT[(4 * t + i) * B + b] = c;
    }
}

// -------------------- K3a: split-K register-tiled GEMM for both GRU cells --------------------
// grid = 48 row-tiles * 24 splits = 1152 blocks (8/SM), 128 threads.
// Thread computes 4 batches x 4 rows. k-tile = 32, K per block = 64.
__global__ void k3a_gemm(const float* __restrict__ h,
                         const float* __restrict__ Wih_f, const float* __restrict__ Whh_f,
                         const float* __restrict__ Wih_b, const float* __restrict__ Whh_b)
{
    int tile  = blockIdx.x / KSPL;
    int split = blockIdx.x % KSPL;
    int R0    = tile * ROWT;           // global row base (0..3071)
    int cell  = (R0 >= 1536) ? 1 : 0;
    int gr0   = R0 - cell * 1536;      // row within this cell's 1536-row W matrix

    const bool   hh   = (split >= 16);
    const float* W    = hh ? (cell ? Whh_b : Whh_f) : (cell ? Wih_b : Wih_f);
    const int    ldw  = hh ? H : D2H;
    const int    koff = hh ? (split - 16) * KPS : split * KPS;

    __shared__ float sW[32][68];       // [k][row], padded
    __shared__ float sX[32][32];       // [k][batch]

    int tid = threadIdx.x;
    int tx  = tid & 7;                 // batch group: batches 4tx..4tx+3
    int ty  = tid >> 3;                // row group:   rows   4ty..4ty+3

    float acc[4][4];
#pragma unroll
    for (int i = 0; i < 4; ++i)
#pragma unroll
        for (int j = 0; j < 4; ++j) acc[i][j] = 0.f;

    const float4* H4  = (const float4*)(h + (size_t)cell * B * H);
    const float4* cT4 = (const float4*)g_cT;

#pragma unroll
    for (int kt = 0; kt < KPS; kt += 32) {
        // --- load W tile: 64 rows x 32 k, transposed into sW[k][row] ---
#pragma unroll
        for (int i = 0; i < 4; ++i) {
            int idx = tid + i * 128;
            int row = idx >> 3, kg = idx & 7;
            const float4* wr = (const float4*)(W + (size_t)(gr0 + row) * ldw + koff + kt);
            float4 w = wr[kg];
            sW[4 * kg + 0][row] = w.x;
            sW[4 * kg + 1][row] = w.y;
            sW[4 * kg + 2][row] = w.z;
            sW[4 * kg + 3][row] = w.w;
        }
        // --- load X tile into sX[k][b] ---
        if (!hh) {
#pragma unroll
            for (int i = 0; i < 2; ++i) {
                int idx = tid + i * 128;
                int k = idx >> 3, bg = idx & 7;
                ((float4*)&sX[k][0])[bg] = cT4[(size_t)(koff + kt + k) * 8 + bg];
            }
        } else {
#pragma unroll
            for (int i = 0; i < 2; ++i) {
                int idx = tid + i * 128;
                int b = idx >> 3, kg = idx & 7;
                float4 hv = H4[(size_t)b * (H / 4) + ((koff + kt) >> 2) + kg];
                sX[4 * kg + 0][b] = hv.x;
                sX[4 * kg + 1][b] = hv.y;
                sX[4 * kg + 2][b] = hv.z;
                sX[4 * kg + 3][b] = hv.w;
            }
        }
        __syncthreads();

#pragma unroll
        for (int k = 0; k < 32; ++k) {
            float4 a = ((const float4*)&sX[k][0])[tx];
            float4 w = *(const float4*)&sW[k][4 * ty];
            acc[0][0] += a.x * w.x; acc[0][1] += a.x * w.y; acc[0][2] += a.x * w.z; acc[0][3] += a.x * w.w;
            acc[1][0] += a.y * w.x; acc[1][1] += a.y * w.y; acc[1][2] += a.y * w.z; acc[1][3] += a.y * w.w;
            acc[2][0] += a.z * w.x; acc[2][1] += a.z * w.y; acc[2][2] += a.z * w.z; acc[2][3] += a.z * w.w;
            acc[3][0] += a.w * w.x; acc[3][1] += a.w * w.y; acc[3][2] += a.w * w.z; acc[3][3] += a.w * w.w;
        }
        __syncthreads();
    }

#pragma unroll
    for (int j = 0; j < 4; ++j)
#pragma unroll
        for (int i = 0; i < 4; ++i)
            g_gpart[split][R0 + 4 * ty + j][4 * tx + i] = acc[i][j];
}

// -------------------- K3b: combine partials + gates + nonlinearity --------------------
__device__ __forceinline__ float sigmoidf_(float x) { return 1.0f / (1.0f + expf(-x)); }

__global__ void k3b_gate(const float* __restrict__ h,
                         const float* __restrict__ bih_f, const float* __restrict__ bhh_f,
                         const float* __restrict__ bih_b, const float* __restrict__ bhh_b,
                         float* __restrict__ out)
{
    int idx  = blockIdx.x * 256 + threadIdx.x;
    int b    = idx & 31;
    int j    = (idx >> 5) & 511;
    int cell = idx >> 14;

    const float* bih = cell ? bih_b : bih_f;
    const float* bhh = cell ? bhh_b : bhh_f;
    int Rb = cell * 1536;

    float Gi[3], Gh[3];
#pragma unroll
    for (int g = 0; g < 3; ++g) {
        int R = Rb + g * 512 + j;
        float gi = bih[g * 512 + j];
#pragma unroll
        for (int s = 0; s < 16; ++s) gi += g_gpart[s][R][b];
        float gh = bhh[g * 512 + j];
#pragma unroll
        for (int s = 16; s < 24; ++s) gh += g_gpart[s][R][b];
        Gi[g] = gi; Gh[g] = gh;
    }
    float hprev = h[(size_t)cell * B * H + b * H + j];
    float r = sigmoidf_(Gi[0] + Gh[0]);
    float z = sigmoidf_(Gi[1] + Gh[1]);
    float n = tanhf(Gi[2] + r * Gh[2]);
    float hn = (1.0f - z) * n + z * hprev;

    out[OUT_HNEW + cell * B * H + b * H + j] = hn;
    if (b == B - 1) g_colast[cell * H + j] = hn;
}

// -------------------- K4: vocab GEMV --------------------
__global__ void k4_logits(const float4* __restrict__ outW, const float* __restrict__ outb)
{
    __shared__ float4 sc[D2H / 4];
    int tid = threadIdx.x;
    sc[tid] = ((const float4*)g_colast)[tid];
    __syncthreads();

    int warp = tid >> 5, lane = tid & 31;
    int v = blockIdx.x * 8 + warp;
    const float4* wrow = outW + (size_t)v * (D2H / 4);
    float acc = 0.f;
#pragma unroll
    for (int i = 0; i < 8; ++i) {
        float4 w = wrow[lane + 32 * i];
        float4 c = sc[lane + 32 * i];
        acc += w.x * c.x + w.y * c.y + w.z * c.z + w.w * c.w;
    }
#pragma unroll
    for (int o = 16; o; o >>= 1) acc += __shfl_xor_sync(0xFFFFFFFFu, acc, o);
    if (lane == 0) g_logits[v] = acc + outb[v];
}

// -------------------- K5a: per-block (max, sumexp) partials --------------------
// grid 32 x 256; grid-stride over 8000 float4
__global__ void k5a_partial()
{
    const float4* L4 = (const float4*)g_logits;
    int tid = threadIdx.x;
    __shared__ float red[8];

    float m = -1e30f;
    for (int i = blockIdx.x * 256 + tid; i < V / 4; i += 32 * 256) {
        float4 v = L4[i];
        m = fmaxf(m, fmaxf(fmaxf(v.x, v.y), fmaxf(v.z, v.w)));
    }
#pragma unroll
    for (int o = 16; o; o >>= 1) m = fmaxf(m, __shfl_xor_sync(0xFFFFFFFFu, m, o));
    if ((tid & 31) == 0) red[tid >> 5] = m;
    __syncthreads();
    float bm = fmaxf(fmaxf(fmaxf(red[0], red[1]), fmaxf(red[2], red[3])),
                     fmaxf(fmaxf(red[4], red[5]), fmaxf(red[6], red[7])));
    __syncthreads();

    float s = 0.f;
    for (int i = blockIdx.x * 256 + tid; i < V / 4; i += 32 * 256) {
        float4 v = L4[i];
        s += expf(v.x - bm) + expf(v.y - bm) + expf(v.z - bm) + expf(v.w - bm);
    }
#pragma unroll
    for (int o = 16; o; o >>= 1) s += __shfl_xor_sync(0xFFFFFFFFu, s, o);
    if ((tid & 31) == 0) red[tid >> 5] = s;
    __syncthreads();
    if (tid == 0) {
        float bs = red[0] + red[1] + red[2] + red[3] + red[4] + red[5] + red[6] + red[7];
        g_lse[blockIdx.x] = make_float2(bm, bs);
    }
}

// -------------------- K5b: combine partials, write logp --------------------
// grid 32 x 256
__global__ void k5b_write(float* __restrict__ out)
{
    // every thread combines the 32 partials (broadcast reads)
    float M = -1e30f;
#pragma unroll
    for (int i = 0; i < 32; ++i) M = fmaxf(M, g_lse[i].x);
    float S = 0.f;
#pragma unroll
    for (int i = 0; i < 32; ++i) { float2 p = g_lse[i]; S += p.y * expf(p.x - M); }
    float lse = M + logf(S);

    const float4* L4 = (const float4*)g_logits;
    float4* O4 = (float4*)(out + OUT_LOGP);
    for (int i = blockIdx.x * 256 + threadIdx.x; i < V / 4; i += 32 * 256) {
        float4 v = L4[i];
        v.x -= lse; v.y -= lse; v.z -= lse; v.w -= lse;
        O4[i] = v;
    }
}

// -------------------- launch --------------------
extern "C" void kernel_launch(void* const* d_in, const int* in_sizes, int n_in,
                              void* d_out, int out_size)
{
    (void)in_sizes; (void)n_in; (void)out_size;
    const float* h_in   = (const float*)d_in[1];
    const float* enc    = (const float*)d_in[2];
    const float* Wih_f  = (const float*)d_in[6];
    const float* Whh_f  = (const float*)d_in[7];
    const float* bih_f  = (const float*)d_in[8];
    const float* bhh_f  = (const float*)d_in[9];
    const float* Wih_b  = (const float*)d_in[10];
    const float* Whh_b  = (const float*)d_in[11];
    const float* bih_b  = (const float*)d_in[12];
    const float* bhh_b  = (const float*)d_in[13];
    const float* outW   = (const float*)d_in[14];
    const float* outb   = (const float*)d_in[15];
    float* out = (float*)d_out;

    k1_reduce<<<dim3(SPLITS, B), 256>>>((const float4*)enc, out);
    k2_finalize<<<B, 256>>>();

    k3a_gemm<<<(NROWS / ROWT) * KSPL, 128>>>(h_in, Wih_f, Whh_f, Wih_b, Whh_b);
    k3b_gate<<<(2 * B * H) / 256, 256>>>(h_in, bih_f, bhh_f, bih_b, bhh_b, out);

    k4_logits<<<V / 8, 256>>>((const float4*)outW, outb);
    k5a_partial<<<32, 256>>>();
    k5b_write<<<32, 256>>>(out);
}

// round 9
// speedup vs baseline: 1.2095x; 1.0175x over previous
#include <cuda_runtime.h>
#include <math.h>

// Problem constants
#define B    32
#define L    2048
#define E    512
#define H    512
#define V    32000
#define D2H  1024          // 2*H
#define SPLITS 32          // L split for k1 reduction

// Output layout (fp32): logp[32000] | h_new[32768] | attn_weights[65536]
#define OUT_LOGP  0
#define OUT_HNEW  32000
#define OUT_ATTN  64768

// GRU GEMM geometry: rows = 2 cells * 3 gates * 512 = 3072, K = 1024(ih) + 512(hh)
#define NROWS 3072
#define ROWT  64            // rows per block tile
#define KSPL  24            // k-splits: 0..15 = ih (64 cols each), 16..23 = hh (64 cols each)
#define KPS   64            // K per split

// -------------------- scratch --------------------
__device__ float4 g_partial[B * SPLITS * (D2H / 4)];   // 4 MB
__device__ float  g_cT[D2H * B];                       // c transposed [k][b]
__device__ float  g_gpart[KSPL][NROWS][B];             // GRU gate partials, 9.4 MB
__device__ float2 g_gsum[NROWS * B];                   // reduced (gi, gh) per (R,b), 786 KB
__device__ float  g_colast[D2H];                       // c_out row 31
__device__ float  g_logits[V];
__device__ float2 g_lse[32];                           // per-block (max, sumexp)

// -------------------- K1: partial reduce of encoder_out over L (+ attn fill) --------------------
__global__ void k1_reduce(const float4* __restrict__ enc, float* __restrict__ out)
{
    int s = blockIdx.x, b = blockIdx.y, t = threadIdx.x;
    int l0 = s * (L / SPLITS);
    float4 acc = make_float4(0.f, 0.f, 0.f, 0.f);
    const float4* base = enc + (size_t)(b * L + l0) * (D2H / 4) + t;
#pragma unroll 8
    for (int l = 0; l < L / SPLITS; ++l) {
        float4 v = base[(size_t)l * (D2H / 4)];
        acc.x += v.x; acc.y += v.y; acc.z += v.z; acc.w += v.w;
    }
    g_partial[(b * SPLITS + s) * (D2H / 4) + t] = acc;

    // fold in constant attn_weights fill: 1024 blocks x 16 float4 = 16384 float4
    if (t < 16) {
        int fid = b * SPLITS + s;
        const float w = 1.0f / (float)L;
        ((float4*)(out + OUT_ATTN))[fid * 16 + t] = make_float4(w, w, w, w);
    }
}

// -------------------- K2: finalize c = relu(mean), store transposed --------------------
__global__ void k2_finalize()
{
    int b = blockIdx.x, t = threadIdx.x;
    float4 acc = make_float4(0.f, 0.f, 0.f, 0.f);
#pragma unroll
    for (int s = 0; s < SPLITS; ++s) {
        float4 v = g_partial[(b * SPLITS + s) * (D2H / 4) + t];
        acc.x += v.x; acc.y += v.y; acc.z += v.z; acc.w += v.w;
    }
    const float inv = 1.0f / (float)L;
    float vals[4] = { acc.x * inv, acc.y * inv, acc.z * inv, acc.w * inv };
#pragma unroll
    for (int i = 0; i < 4; ++i) {
        float c = vals[i] > 0.f ? vals[i] : 0.f;
        g_cT[(4 * t + i) * B + b] = c;
    }
}

// -------------------- K3a: split-K register-tiled GEMM for both GRU cells --------------------
// grid = 48 row-tiles * 24 splits = 1152 blocks (8/SM), 128 threads.
__global__ void k3a_gemm(const float* __restrict__ h,
                         const float* __restrict__ Wih_f, const float* __restrict__ Whh_f,
                         const float* __restrict__ Wih_b, const float* __restrict__ Whh_b)
{
    int tile  = blockIdx.x / KSPL;
    int split = blockIdx.x % KSPL;
    int R0    = tile * ROWT;           // global row base (0..3071)
    int cell  = (R0 >= 1536) ? 1 : 0;
    int gr0   = R0 - cell * 1536;      // row within this cell's 1536-row W matrix

    const bool   hh   = (split >= 16);
    const float* W    = hh ? (cell ? Whh_b : Whh_f) : (cell ? Wih_b : Wih_f);
    const int    ldw  = hh ? H : D2H;
    const int    koff = hh ? (split - 16) * KPS : split * KPS;

    __shared__ float sW[32][68];       // [k][row], padded
    __shared__ float sX[32][32];       // [k][batch]

    int tid = threadIdx.x;
    int tx  = tid & 7;                 // batch group: batches 4tx..4tx+3
    int ty  = tid >> 3;                // row group:   rows   4ty..4ty+3

    float acc[4][4];
#pragma unroll
    for (int i = 0; i < 4; ++i)
#pragma unroll
        for (int j = 0; j < 4; ++j) acc[i][j] = 0.f;

    const float4* H4  = (const float4*)(h + (size_t)cell * B * H);
    const float4* cT4 = (const float4*)g_cT;

#pragma unroll
    for (int kt = 0; kt < KPS; kt += 32) {
        // --- load W tile: 64 rows x 32 k, transposed into sW[k][row] ---
#pragma unroll
        for (int i = 0; i < 4; ++i) {
            int idx = tid + i * 128;
            int row = idx >> 3, kg = idx & 7;
            const float4* wr = (const float4*)(W + (size_t)(gr0 + row) * ldw + koff + kt);
            float4 w = wr[kg];
            sW[4 * kg + 0][row] = w.x;
            sW[4 * kg + 1][row] = w.y;
            sW[4 * kg + 2][row] = w.z;
            sW[4 * kg + 3][row] = w.w;
        }
        // --- load X tile into sX[k][b] ---
        if (!hh) {
#pragma unroll
            for (int i = 0; i < 2; ++i) {
                int idx = tid + i * 128;
                int k = idx >> 3, bg = idx & 7;
                ((float4*)&sX[k][0])[bg] = cT4[(size_t)(koff + kt + k) * 8 + bg];
            }
        } else {
#pragma unroll
            for (int i = 0; i < 2; ++i) {
                int idx = tid + i * 128;
                int b = idx >> 3, kg = idx & 7;
                float4 hv = H4[(size_t)b * (H / 4) + ((koff + kt) >> 2) + kg];
                sX[4 * kg + 0][b] = hv.x;
                sX[4 * kg + 1][b] = hv.y;
                sX[4 * kg + 2][b] = hv.z;
                sX[4 * kg + 3][b] = hv.w;
            }
        }
        __syncthreads();

#pragma unroll
        for (int k = 0; k < 32; ++k) {
            float4 a = ((const float4*)&sX[k][0])[tx];
            float4 w = *(const float4*)&sW[k][4 * ty];
            acc[0][0] += a.x * w.x; acc[0][1] += a.x * w.y; acc[0][2] += a.x * w.z; acc[0][3] += a.x * w.w;
            acc[1][0] += a.y * w.x; acc[1][1] += a.y * w.y; acc[1][2] += a.y * w.z; acc[1][3] += a.y * w.w;
            acc[2][0] += a.z * w.x; acc[2][1] += a.z * w.y; acc[2][2] += a.z * w.z; acc[2][3] += a.z * w.w;
            acc[3][0] += a.w * w.x; acc[3][1] += a.w * w.y; acc[3][2] += a.w * w.z; acc[3][3] += a.w * w.w;
        }
        __syncthreads();
    }

#pragma unroll
    for (int j = 0; j < 4; ++j)
#pragma unroll
        for (int i = 0; i < 4; ++i)
            g_gpart[split][R0 + 4 * ty + j][4 * tx + i] = acc[i][j];
}

// -------------------- K3b1: reduce 24 split-partials -> (gi, gh) per (R,b) --------------------
// grid 384 x 256. Loads staged into a register array so ptxas front-batches 24
// independent LDGs (MLP ~24) instead of a load+add dependent chain.
__global__ void k3b1_reduce()
{
    int idx = blockIdx.x * 256 + threadIdx.x;   // 0..98303
    int b   = idx & 31;
    int R   = idx >> 5;

    float v[KSPL];
#pragma unroll
    for (int s = 0; s < KSPL; ++s) v[s] = g_gpart[s][R][b];

    float gi = 0.f, gh = 0.f;
#pragma unroll
    for (int s = 0; s < 16; ++s) gi += v[s];
#pragma unroll
    for (int s = 16; s < 24; ++s) gh += v[s];

    g_gsum[idx] = make_float2(gi, gh);
}

// -------------------- K3b2: gate math + nonlinearity --------------------
__device__ __forceinline__ float sigmoidf_(float x) { return 1.0f / (1.0f + expf(-x)); }

__global__ void k3b2_gate(const float* __restrict__ h,
                          const float* __restrict__ bih_f, const float* __restrict__ bhh_f,
                          const float* __restrict__ bih_b, const float* __restrict__ bhh_b,
                          float* __restrict__ out)
{
    int idx  = blockIdx.x * 256 + threadIdx.x;
    int b    = idx & 31;
    int j    = (idx >> 5) & 511;
    int cell = idx >> 14;

    const float* bih = cell ? bih_b : bih_f;
    const float* bhh = cell ? bhh_b : bhh_f;
    int Rb = cell * 1536;

    float2 pr = g_gsum[(Rb +           j) * B + b];
    float2 pz = g_gsum[(Rb +  512 +    j) * B + b];
    float2 pn = g_gsum[(Rb + 1024 +    j) * B + b];

    float Gir = pr.x + bih[j],          Ghr = pr.y + bhh[j];
    float Giz = pz.x + bih[512 + j],    Ghz = pz.y + bhh[512 + j];
    float Gin = pn.x + bih[1024 + j],   Ghn = pn.y + bhh[1024 + j];

    float hprev = h[(size_t)cell * B * H + b * H + j];
    float r = sigmoidf_(Gir + Ghr);
    float z = sigmoidf_(Giz + Ghz);
    float n = tanhf(Gin + r * Ghn);
    float hn = (1.0f - z) * n + z * hprev;

    out[OUT_HNEW + cell * B * H + b * H + j] = hn;
    if (b == B - 1) g_colast[cell * H + j] = hn;
}

// -------------------- K4: vocab GEMV --------------------
__global__ void k4_logits(const float4* __restrict__ outW, const float* __restrict__ outb)
{
    __shared__ float4 sc[D2H / 4];
    int tid = threadIdx.x;
    sc[tid] = ((const float4*)g_colast)[tid];
    __syncthreads();

    int warp = tid >> 5, lane = tid & 31;
    int v = blockIdx.x * 8 + warp;
    const float4* wrow = outW + (size_t)v * (D2H / 4);
    float acc = 0.f;
#pragma unroll
    for (int i = 0; i < 8; ++i) {
        float4 w = wrow[lane + 32 * i];
        float4 c = sc[lane + 32 * i];
        acc += w.x * c.x + w.y * c.y + w.z * c.z + w.w * c.w;
    }
#pragma unroll
    for (int o = 16; o; o >>= 1) acc += __shfl_xor_sync(0xFFFFFFFFu, acc, o);
    if (lane == 0) g_logits[v] = acc + outb[v];
}

// -------------------- K5a: per-block (max, sumexp) partials --------------------
__global__ void k5a_partial()
{
    const float4* L4 = (const float4*)g_logits;
    int tid = threadIdx.x;
    __shared__ float red[8];

    float m = -1e30f;
    for (int i = blockIdx.x * 256 + tid; i < V / 4; i += 32 * 256) {
        float4 v = L4[i];
        m = fmaxf(m, fmaxf(fmaxf(v.x, v.y), fmaxf(v.z, v.w)));
    }
#pragma unroll
    for (int o = 16; o; o >>= 1) m = fmaxf(m, __shfl_xor_sync(0xFFFFFFFFu, m, o));
    if ((tid & 31) == 0) red[tid >> 5] = m;
    __syncthreads();
    float bm = fmaxf(fmaxf(fmaxf(red[0], red[1]), fmaxf(red[2], red[3])),
                     fmaxf(fmaxf(red[4], red[5]), fmaxf(red[6], red[7])));
    __syncthreads();

    float s = 0.f;
    for (int i = blockIdx.x * 256 + tid; i < V / 4; i += 32 * 256) {
        float4 v = L4[i];
        s += expf(v.x - bm) + expf(v.y - bm) + expf(v.z - bm) + expf(v.w - bm);
    }
#pragma unroll
    for (int o = 16; o; o >>= 1) s += __shfl_xor_sync(0xFFFFFFFFu, s, o);
    if ((tid & 31) == 0) red[tid >> 5] = s;
    __syncthreads();
    if (tid == 0) {
        float bs = red[0] + red[1] + red[2] + red[3] + red[4] + red[5] + red[6] + red[7];
        g_lse[blockIdx.x] = make_float2(bm, bs);
    }
}

// -------------------- K5b: combine partials, write logp --------------------
__global__ void k5b_write(float* __restrict__ out)
{
    float M = -1e30f;
#pragma unroll
    for (int i = 0; i < 32; ++i) M = fmaxf(M, g_lse[i].x);
    float S = 0.f;
#pragma unroll
    for (int i = 0; i < 32; ++i) { float2 p = g_lse[i]; S += p.y * expf(p.x - M); }
    float lse = M + logf(S);

    const float4* L4 = (const float4*)g_logits;
    float4* O4 = (float4*)(out + OUT_LOGP);
    for (int i = blockIdx.x * 256 + threadIdx.x; i < V / 4; i += 32 * 256) {
        float4 v = L4[i];
        v.x -= lse; v.y -= lse; v.z -= lse; v.w -= lse;
        O4[i] = v;
    }
}

// -------------------- launch --------------------
extern "C" void kernel_launch(void* const* d_in, const int* in_sizes, int n_in,
                              void* d_out, int out_size)
{
    (void)in_sizes; (void)n_in; (void)out_size;
    const float* h_in   = (const float*)d_in[1];
    const float* enc    = (const float*)d_in[2];
    const float* Wih_f  = (const float*)d_in[6];
    const float* Whh_f  = (const float*)d_in[7];
    const float* bih_f  = (const float*)d_in[8];
    const float* bhh_f  = (const float*)d_in[9];
    const float* Wih_b  = (const float*)d_in[10];
    const float* Whh_b  = (const float*)d_in[11];
    const float* bih_b  = (const float*)d_in[12];
    const float* bhh_b  = (const float*)d_in[13];
    const float* outW   = (const float*)d_in[14];
    const float* outb   = (const float*)d_in[15];
    float* out = (float*)d_out;

    k1_reduce<<<dim3(SPLITS, B), 256>>>((const float4*)enc, out);
    k2_finalize<<<B, 256>>>();

    k3a_gemm<<<(NROWS / ROWT) * KSPL, 128>>>(h_in, Wih_f, Whh_f, Wih_b, Whh_b);
    k3b1_reduce<<<(NROWS * B) / 256, 256>>>();
    k3b2_gate<<<(2 * B * H) / 256, 256>>>(h_in, bih_f, bhh_f, bih_b, bhh_b, out);

    k4_logits<<<V / 8, 256>>>((const float4*)outW, outb);
    k5a_partial<<<32, 256>>>();
    k5b_write<<<32, 256>>>(out);
}